// round 1
// baseline (speedup 1.0000x reference)
#include <cuda_runtime.h>
#include <math.h>
#include <stdint.h>

// Problem constants
#define BB   32
#define TT   256
#define HH   768
#define LL   12
#define NHH  12
#define DHH  64
#define FFF  3072
#define NLL  31
#define BTT  (BB*TT)          // 8192
#define START_S 21
#define NEGV (-10000.0f)

// ---------------------------------------------------------------------------
// Static device scratch (no runtime allocation allowed)
// ---------------------------------------------------------------------------
__device__ float g_x   [BTT*HH];
__device__ float g_q   [BTT*HH];
__device__ float g_k   [BTT*HH];
__device__ float g_v   [BTT*HH];
__device__ float g_ctx [BTT*HH];
__device__ float g_t1  [BTT*HH];
__device__ float g_ff  [BTT*FFF];           // doubles as attention-score buffer (same size)
__device__ float g_feats[BTT*NLL];
__device__ int   g_psi [(TT-1)*BB*NLL];

// ---------------------------------------------------------------------------
// Helpers
// ---------------------------------------------------------------------------
__device__ __forceinline__ float block_reduce_sum(float v, float* red) {
    int tid = threadIdx.x;
    red[tid] = v;
    __syncthreads();
    for (int s = blockDim.x >> 1; s > 0; s >>= 1) {
        if (tid < s) red[tid] += red[tid + s];
        __syncthreads();
    }
    float r = red[0];
    __syncthreads();
    return r;
}

__device__ __forceinline__ float gelu_exact(float x) {
    return 0.5f * x * (1.0f + erff(x * 0.70710678118654752440f));
}

// ---------------------------------------------------------------------------
// Embedding + LayerNorm:  x = LN(tok[id] + pos[t] + typ[0]) * g + b
// one block per row (B*T rows), 256 threads
// ---------------------------------------------------------------------------
__global__ void embed_ln_kernel(const int* __restrict__ ids,
                                const float* __restrict__ tok,
                                const float* __restrict__ pos,
                                const float* __restrict__ typ,
                                const float* __restrict__ gamma,
                                const float* __restrict__ beta) {
    __shared__ float sx[HH];
    __shared__ float red[256];
    int row = blockIdx.x;
    int t   = row & (TT - 1);
    int id  = ids[row];
    for (int h = threadIdx.x; h < HH; h += 256)
        sx[h] = tok[(size_t)id * HH + h] + pos[t * HH + h] + typ[h];
    __syncthreads();
    float s = 0.f;
    for (int h = threadIdx.x; h < HH; h += 256) s += sx[h];
    float mu = block_reduce_sum(s, red) * (1.0f / HH);
    float s2 = 0.f;
    for (int h = threadIdx.x; h < HH; h += 256) { float d = sx[h] - mu; s2 += d * d; }
    float var = block_reduce_sum(s2, red) * (1.0f / HH);
    float inv = rsqrtf(var + 1e-12f);
    for (int h = threadIdx.x; h < HH; h += 256)
        g_x[(size_t)row * HH + h] = (sx[h] - mu) * inv * gamma[h] + beta[h];
}

// ---------------------------------------------------------------------------
// Residual + LayerNorm:  out = LN(res + y) * g + b  (in-place safe: row buffered)
// ---------------------------------------------------------------------------
__global__ void ln_res_kernel(const float* __restrict__ res,
                              const float* __restrict__ y,
                              const float* __restrict__ gamma,
                              const float* __restrict__ beta,
                              float* __restrict__ out) {
    __shared__ float sx[HH];
    __shared__ float red[256];
    size_t base = (size_t)blockIdx.x * HH;
    for (int h = threadIdx.x; h < HH; h += 256)
        sx[h] = res[base + h] + y[base + h];
    __syncthreads();
    float s = 0.f;
    for (int h = threadIdx.x; h < HH; h += 256) s += sx[h];
    float mu = block_reduce_sum(s, red) * (1.0f / HH);
    float s2 = 0.f;
    for (int h = threadIdx.x; h < HH; h += 256) { float d = sx[h] - mu; s2 += d * d; }
    float var = block_reduce_sum(s2, red) * (1.0f / HH);
    float inv = rsqrtf(var + 1e-12f);
    for (int h = threadIdx.x; h < HH; h += 256)
        out[base + h] = (sx[h] - mu) * inv * gamma[h] + beta[h];
}

// ---------------------------------------------------------------------------
// Classic fp32 SGEMM: C[M,N] = act(A[M,K] @ B[K,N] + bias)
// 128x128 block tile, BK=8, 256 threads, 8x8 per-thread (4+4 split fragments)
// M,N multiples of 128; K multiple of 8.
// ---------------------------------------------------------------------------
__global__ __launch_bounds__(256, 2)
void sgemm_kernel(const float* __restrict__ A, const float* __restrict__ B,
                  const float* __restrict__ bias, float* __restrict__ C,
                  int M, int N, int K, int act) {
    __shared__ float As[8][128];
    __shared__ float Bs[8][128];
    const int tid = threadIdx.x;
    const int tx = tid & 15, ty = tid >> 4;
    const int bx = blockIdx.x, by = blockIdx.y;
    const float* Ab = A + (size_t)by * 128 * K;
    const float* Bb = B + bx * 128;
    const int arow = tid >> 1, acol = (tid & 1) << 2;
    const int brow = tid >> 5, bcol = (tid & 31) << 2;

    float acc[8][8];
#pragma unroll
    for (int i = 0; i < 8; i++)
#pragma unroll
        for (int j = 0; j < 8; j++) acc[i][j] = 0.f;

    for (int k0 = 0; k0 < K; k0 += 8) {
        float4 av = *(const float4*)(Ab + (size_t)arow * K + k0 + acol);
        As[acol + 0][arow] = av.x; As[acol + 1][arow] = av.y;
        As[acol + 2][arow] = av.z; As[acol + 3][arow] = av.w;
        *(float4*)(&Bs[brow][bcol]) = *(const float4*)(Bb + (size_t)(k0 + brow) * N + bcol);
        __syncthreads();
#pragma unroll
        for (int kk = 0; kk < 8; kk++) {
            float4 a0 = *(const float4*)&As[kk][ty * 4];
            float4 a1 = *(const float4*)&As[kk][64 + ty * 4];
            float4 b0 = *(const float4*)&Bs[kk][tx * 4];
            float4 b1 = *(const float4*)&Bs[kk][64 + tx * 4];
            float ar[8] = {a0.x, a0.y, a0.z, a0.w, a1.x, a1.y, a1.z, a1.w};
            float br[8] = {b0.x, b0.y, b0.z, b0.w, b1.x, b1.y, b1.z, b1.w};
#pragma unroll
            for (int i = 0; i < 8; i++)
#pragma unroll
                for (int j = 0; j < 8; j++) acc[i][j] += ar[i] * br[j];
        }
        __syncthreads();
    }
#pragma unroll
    for (int i = 0; i < 8; i++) {
        int r = by * 128 + ((i < 4) ? (ty * 4 + i) : (64 + ty * 4 + (i - 4)));
#pragma unroll
        for (int jh = 0; jh < 2; jh++) {
            int c = bx * 128 + jh * 64 + tx * 4;
            float o0 = acc[i][jh * 4 + 0] + bias[c + 0];
            float o1 = acc[i][jh * 4 + 1] + bias[c + 1];
            float o2 = acc[i][jh * 4 + 2] + bias[c + 2];
            float o3 = acc[i][jh * 4 + 3] + bias[c + 3];
            if (act == 1) { o0 = gelu_exact(o0); o1 = gelu_exact(o1); o2 = gelu_exact(o2); o3 = gelu_exact(o3); }
            float4 o = make_float4(o0, o1, o2, o3);
            *(float4*)(C + (size_t)r * N + c) = o;
        }
    }
}

// ---------------------------------------------------------------------------
// Attention scores: S[hb, 256, 256] = Q_h @ K_h^T * (1/8) + amask
// hb = b*NH + h. Q/K rows strided by HH. Grid (2,2,384), 256 threads.
// ---------------------------------------------------------------------------
__global__ __launch_bounds__(256, 2)
void attn_score_kernel(const float* __restrict__ Q, const float* __restrict__ Km,
                       const int* __restrict__ maskp, float* __restrict__ S) {
    __shared__ float As[8][128];
    __shared__ float Bs[8][128];
    const int hb = blockIdx.z;
    const int b = hb / NHH, h = hb % NHH;
    const float* Qb = Q + (size_t)b * TT * HH + h * DHH;
    const float* Kb = Km + (size_t)b * TT * HH + h * DHH;
    float* Sb = S + (size_t)hb * TT * TT;
    const int tid = threadIdx.x;
    const int tx = tid & 15, ty = tid >> 4;
    const int bx = blockIdx.x, by = blockIdx.y;
    const int arow = tid >> 1, acol = (tid & 1) << 2;
    const int nrow = tid >> 1, kg = (tid & 1) << 2;

    float acc[8][8];
#pragma unroll
    for (int i = 0; i < 8; i++)
#pragma unroll
        for (int j = 0; j < 8; j++) acc[i][j] = 0.f;

    for (int k0 = 0; k0 < DHH; k0 += 8) {
        float4 av = *(const float4*)(Qb + (size_t)(by * 128 + arow) * HH + k0 + acol);
        As[acol + 0][arow] = av.x; As[acol + 1][arow] = av.y;
        As[acol + 2][arow] = av.z; As[acol + 3][arow] = av.w;
        float4 kv = *(const float4*)(Kb + (size_t)(bx * 128 + nrow) * HH + k0 + kg);
        Bs[kg + 0][nrow] = kv.x; Bs[kg + 1][nrow] = kv.y;
        Bs[kg + 2][nrow] = kv.z; Bs[kg + 3][nrow] = kv.w;
        __syncthreads();
#pragma unroll
        for (int kk = 0; kk < 8; kk++) {
            float4 a0 = *(const float4*)&As[kk][ty * 4];
            float4 a1 = *(const float4*)&As[kk][64 + ty * 4];
            float4 b0 = *(const float4*)&Bs[kk][tx * 4];
            float4 b1 = *(const float4*)&Bs[kk][64 + tx * 4];
            float ar[8] = {a0.x, a0.y, a0.z, a0.w, a1.x, a1.y, a1.z, a1.w};
            float br[8] = {b0.x, b0.y, b0.z, b0.w, b1.x, b1.y, b1.z, b1.w};
#pragma unroll
            for (int i = 0; i < 8; i++)
#pragma unroll
                for (int j = 0; j < 8; j++) acc[i][j] += ar[i] * br[j];
        }
        __syncthreads();
    }
#pragma unroll
    for (int i = 0; i < 8; i++) {
        int r = by * 128 + ((i < 4) ? (ty * 4 + i) : (64 + ty * 4 + (i - 4)));
#pragma unroll
        for (int jh = 0; jh < 2; jh++) {
            int c = bx * 128 + jh * 64 + tx * 4;
            float4 o;
            o.x = acc[i][jh * 4 + 0] * 0.125f + (1.0f - (float)maskp[b * TT + c + 0]) * NEGV;
            o.y = acc[i][jh * 4 + 1] * 0.125f + (1.0f - (float)maskp[b * TT + c + 1]) * NEGV;
            o.z = acc[i][jh * 4 + 2] * 0.125f + (1.0f - (float)maskp[b * TT + c + 2]) * NEGV;
            o.w = acc[i][jh * 4 + 3] * 0.125f + (1.0f - (float)maskp[b * TT + c + 3]) * NEGV;
            *(float4*)(Sb + (size_t)r * TT + c) = o;
        }
    }
}

// ---------------------------------------------------------------------------
// Row softmax over 256 (one warp per row). exact expf to track fp32 reference.
// ---------------------------------------------------------------------------
__global__ void softmax_kernel(float* __restrict__ S) {
    int row  = blockIdx.x * 8 + (threadIdx.x >> 5);
    int lane = threadIdx.x & 31;
    float* r = S + (size_t)row * TT;
    float v[8];
    float mx = -3.4e38f;
#pragma unroll
    for (int i = 0; i < 8; i++) { v[i] = r[lane + 32 * i]; mx = fmaxf(mx, v[i]); }
#pragma unroll
    for (int off = 16; off; off >>= 1) mx = fmaxf(mx, __shfl_xor_sync(0xffffffffu, mx, off));
    float sum = 0.f;
#pragma unroll
    for (int i = 0; i < 8; i++) { v[i] = expf(v[i] - mx); sum += v[i]; }
#pragma unroll
    for (int off = 16; off; off >>= 1) sum += __shfl_xor_sync(0xffffffffu, sum, off);
    float inv = 1.0f / sum;
#pragma unroll
    for (int i = 0; i < 8; i++) r[lane + 32 * i] = v[i] * inv;
}

// ---------------------------------------------------------------------------
// ctx_h = P_h @ V_h  : per head [256,256]@[256,64]. 128 threads, 128x64 tile.
// Grid (1, 2, 384).
// ---------------------------------------------------------------------------
__global__ __launch_bounds__(128, 4)
void attn_pv_kernel(const float* __restrict__ P, const float* __restrict__ V,
                    float* __restrict__ ctx) {
    __shared__ float As[8][128];
    __shared__ float Bs[8][64];
    const int hb = blockIdx.z;
    const int b = hb / NHH, h = hb % NHH;
    const float* Pb = P + (size_t)hb * TT * TT;
    const float* Vb = V + (size_t)b * TT * HH + h * DHH;
    float* Cb = ctx + (size_t)b * TT * HH + h * DHH;
    const int by = blockIdx.y;
    const int tid = threadIdx.x;
    const int tx = tid & 7, ty = tid >> 3;
    const int brow = tid >> 4, bcol = (tid & 15) << 2;

    float acc[8][8];
#pragma unroll
    for (int i = 0; i < 8; i++)
#pragma unroll
        for (int j = 0; j < 8; j++) acc[i][j] = 0.f;

    for (int k0 = 0; k0 < TT; k0 += 8) {
        float4 a0 = *(const float4*)(Pb + (size_t)(by * 128 + tid) * TT + k0);
        float4 a1 = *(const float4*)(Pb + (size_t)(by * 128 + tid) * TT + k0 + 4);
        As[0][tid] = a0.x; As[1][tid] = a0.y; As[2][tid] = a0.z; As[3][tid] = a0.w;
        As[4][tid] = a1.x; As[5][tid] = a1.y; As[6][tid] = a1.z; As[7][tid] = a1.w;
        *(float4*)(&Bs[brow][bcol]) = *(const float4*)(Vb + (size_t)(k0 + brow) * HH + bcol);
        __syncthreads();
#pragma unroll
        for (int kk = 0; kk < 8; kk++) {
            float4 aa0 = *(const float4*)&As[kk][ty * 4];
            float4 aa1 = *(const float4*)&As[kk][64 + ty * 4];
            float4 bb0 = *(const float4*)&Bs[kk][tx * 4];
            float4 bb1 = *(const float4*)&Bs[kk][32 + tx * 4];
            float ar[8] = {aa0.x, aa0.y, aa0.z, aa0.w, aa1.x, aa1.y, aa1.z, aa1.w};
            float br[8] = {bb0.x, bb0.y, bb0.z, bb0.w, bb1.x, bb1.y, bb1.z, bb1.w};
#pragma unroll
            for (int i = 0; i < 8; i++)
#pragma unroll
                for (int j = 0; j < 8; j++) acc[i][j] += ar[i] * br[j];
        }
        __syncthreads();
    }
#pragma unroll
    for (int i = 0; i < 8; i++) {
        int r = by * 128 + ((i < 4) ? (ty * 4 + i) : (64 + ty * 4 + (i - 4)));
#pragma unroll
        for (int jh = 0; jh < 2; jh++) {
            int c = jh * 32 + tx * 4;
            float4 o = make_float4(acc[i][jh * 4 + 0], acc[i][jh * 4 + 1],
                                   acc[i][jh * 4 + 2], acc[i][jh * 4 + 3]);
            *(float4*)(Cb + (size_t)r * HH + c) = o;
        }
    }
}

// ---------------------------------------------------------------------------
// feats = x @ lab_W + lab_b  :  [8192,768]@[768,31]
// one block per row; 256 threads = 8 partials x 32 states
// ---------------------------------------------------------------------------
__global__ void feats_kernel(const float* __restrict__ X, const float* __restrict__ W,
                             const float* __restrict__ bias, float* __restrict__ F) {
    __shared__ float sx[HH];
    __shared__ float red[8][32];
    int row = blockIdx.x;
    for (int h = threadIdx.x; h < HH; h += 256) sx[h] = X[(size_t)row * HH + h];
    __syncthreads();
    int j = threadIdx.x & 31, part = threadIdx.x >> 5;
    float s = 0.f;
    if (j < NLL) {
        int k0 = part * 96;
#pragma unroll 4
        for (int k = k0; k < k0 + 96; k++) s += sx[k] * W[k * NLL + j];
    }
    red[part][j] = s;
    __syncthreads();
    if (part == 0 && j < NLL) {
        float tot = bias[j];
#pragma unroll
        for (int p = 0; p < 8; p++) tot += red[p][j];
        F[row * NLL + j] = tot;
    }
}

// ---------------------------------------------------------------------------
// Viterbi decode. One block, 32 warps: warp b handles batch b; lane j = state.
// Matches jnp.argmax first-occurrence tie-breaking.
// Writes score + path to out (as float), layout depends on out_size.
// ---------------------------------------------------------------------------
__global__ void viterbi_kernel(const float* __restrict__ F, const float* __restrict__ trans,
                               float* __restrict__ out, int out_size) {
    __shared__ float tr[NLL][32];
    int tid = threadIdx.x;
    for (int i = tid; i < NLL * NLL; i += blockDim.x)
        tr[i / NLL][i % NLL] = trans[i];
    __syncthreads();
    int b = tid >> 5, j = tid & 31;
    int jc = (j < NLL) ? j : 0;
    float ld = (j == START_S) ? 0.0f : NEGV;
    if (j >= NLL) ld = -1e30f;
    for (int t = 1; t < TT; t++) {
        float best = -3.4e38f; int bp = 0;
#pragma unroll
        for (int prev = 0; prev < NLL; prev++) {
            float ldp = __shfl_sync(0xffffffffu, ld, prev);
            float v = tr[jc][prev] + ldp;
            if (v > best) { best = v; bp = prev; }
        }
        if (j < NLL) g_psi[((t - 1) * BB + b) * NLL + j] = bp;
        float f = (j < NLL) ? F[((size_t)b * TT + t) * NLL + j] : 0.f;
        ld = best + f;
        if (j >= NLL) ld = -1e30f;
    }
    // argmax over lanes 0..30 (first occurrence on ties)
    float val = (j < NLL) ? ld : -3.4e38f;
    int idx = jc;
#pragma unroll
    for (int off = 16; off; off >>= 1) {
        float ov = __shfl_xor_sync(0xffffffffu, val, off);
        int   oi = __shfl_xor_sync(0xffffffffu, idx, off);
        if (ov > val || (ov == val && oi < idx)) { val = ov; idx = oi; }
    }
    if (j == 0) {
        float* score_out = out;
        float* path_out  = out + BB;
        bool have_score = true, have_path = true;
        if (out_size >= BB + BB * TT) { /* default layout */ }
        else if (out_size >= BB * TT) { have_score = false; path_out = out; }
        else { have_path = false; }
        if (have_score) score_out[b] = val;
        if (have_path) {
            int p = idx;
            path_out[b * TT + TT - 1] = (float)p;
            for (int t = TT - 1; t >= 1; t--) {
                p = g_psi[((t - 1) * BB + b) * NLL + p];
                path_out[b * TT + t - 1] = (float)p;
            }
        }
    }
}

// ---------------------------------------------------------------------------
// Launcher
// ---------------------------------------------------------------------------
extern "C" void kernel_launch(void* const* d_in, const int* in_sizes, int n_in,
                              void* d_out, int out_size) {
    const int*   ids    = (const int*)  d_in[0];
    const int*   maskp  = (const int*)  d_in[1];
    const float* tok    = (const float*)d_in[2];
    const float* pos    = (const float*)d_in[3];
    const float* typ    = (const float*)d_in[4];
    const float* eg     = (const float*)d_in[5];
    const float* eb     = (const float*)d_in[6];
    const float* Wq_all = (const float*)d_in[7];
    const float* bq_all = (const float*)d_in[8];
    const float* Wk_all = (const float*)d_in[9];
    const float* bk_all = (const float*)d_in[10];
    const float* Wv_all = (const float*)d_in[11];
    const float* bv_all = (const float*)d_in[12];
    const float* Wo_all = (const float*)d_in[13];
    const float* bo_all = (const float*)d_in[14];
    const float* ln1g   = (const float*)d_in[15];
    const float* ln1b   = (const float*)d_in[16];
    const float* W1_all = (const float*)d_in[17];
    const float* b1_all = (const float*)d_in[18];
    const float* W2_all = (const float*)d_in[19];
    const float* b2_all = (const float*)d_in[20];
    const float* ln2g   = (const float*)d_in[21];
    const float* ln2b   = (const float*)d_in[22];
    const float* labW   = (const float*)d_in[23];
    const float* labb   = (const float*)d_in[24];
    const float* trans  = (const float*)d_in[25];
    float* out = (float*)d_out;

    static float *p_x = nullptr, *p_q, *p_k, *p_v, *p_ctx, *p_t1, *p_ff, *p_feats;
    if (!p_x) {
        cudaGetSymbolAddress((void**)&p_x,    g_x);
        cudaGetSymbolAddress((void**)&p_q,    g_q);
        cudaGetSymbolAddress((void**)&p_k,    g_k);
        cudaGetSymbolAddress((void**)&p_v,    g_v);
        cudaGetSymbolAddress((void**)&p_ctx,  g_ctx);
        cudaGetSymbolAddress((void**)&p_t1,   g_t1);
        cudaGetSymbolAddress((void**)&p_ff,   g_ff);
        cudaGetSymbolAddress((void**)&p_feats,g_feats);
    }

    embed_ln_kernel<<<BTT, 256>>>(ids, tok, pos, typ, eg, eb);

    dim3 gHH(HH / 128, BTT / 128);    // 6 x 64
    dim3 gFF(FFF / 128, BTT / 128);   // 24 x 64
    dim3 gScore(2, 2, BB * NHH);      // 2x2x384
    dim3 gPV(1, 2, BB * NHH);         // 1x2x384

    for (int l = 0; l < LL; l++) {
        const float* Wq = Wq_all + (size_t)l * HH * HH;
        const float* Wk = Wk_all + (size_t)l * HH * HH;
        const float* Wv = Wv_all + (size_t)l * HH * HH;
        const float* Wo = Wo_all + (size_t)l * HH * HH;
        const float* W1 = W1_all + (size_t)l * HH * FFF;
        const float* W2 = W2_all + (size_t)l * FFF * HH;
        const float* bq = bq_all + l * HH;
        const float* bk = bk_all + l * HH;
        const float* bv = bv_all + l * HH;
        const float* bo = bo_all + l * HH;
        const float* b1 = b1_all + l * FFF;
        const float* b2 = b2_all + l * HH;
        const float* g1 = ln1g + l * HH; const float* be1 = ln1b + l * HH;
        const float* g2 = ln2g + l * HH; const float* be2 = ln2b + l * HH;

        sgemm_kernel<<<gHH, 256>>>(p_x, Wq, bq, p_q, BTT, HH, HH, 0);
        sgemm_kernel<<<gHH, 256>>>(p_x, Wk, bk, p_k, BTT, HH, HH, 0);
        sgemm_kernel<<<gHH, 256>>>(p_x, Wv, bv, p_v, BTT, HH, HH, 0);

        attn_score_kernel<<<gScore, 256>>>(p_q, p_k, maskp, p_ff);
        softmax_kernel<<<(BB * NHH * TT) / 8, 256>>>(p_ff);
        attn_pv_kernel<<<gPV, 128>>>(p_ff, p_v, p_ctx);

        sgemm_kernel<<<gHH, 256>>>(p_ctx, Wo, bo, p_t1, BTT, HH, HH, 0);
        ln_res_kernel<<<BTT, 256>>>(p_x, p_t1, g1, be1, p_x);

        sgemm_kernel<<<gFF, 256>>>(p_x, W1, b1, p_ff, BTT, FFF, HH, 1);
        sgemm_kernel<<<gHH, 256>>>(p_ff, W2, b2, p_t1, BTT, HH, FFF, 0);
        ln_res_kernel<<<BTT, 256>>>(p_x, p_t1, g2, be2, p_x);
    }

    feats_kernel<<<BTT, 256>>>(p_x, labW, labb, p_feats);
    viterbi_kernel<<<1, 1024>>>(p_feats, trans, out, out_size);
}

// round 2
// speedup vs baseline: 1.0012x; 1.0012x over previous
#include <cuda_runtime.h>
#include <math.h>
#include <stdint.h>

// Problem constants
#define BB   32
#define TT   256
#define HH   768
#define LL   12
#define NHH  12
#define DHH  64
#define FFF  3072
#define NLL  31
#define BTT  (BB*TT)          // 8192
#define START_S 21
#define NEGV (-10000.0f)

// ---------------------------------------------------------------------------
// Static device scratch (no runtime allocation allowed)
// ---------------------------------------------------------------------------
__device__ float g_x   [BTT*HH];
__device__ float g_q   [BTT*HH];
__device__ float g_k   [BTT*HH];
__device__ float g_v   [BTT*HH];
__device__ float g_ctx [BTT*HH];
__device__ float g_t1  [BTT*HH];
__device__ float g_ff  [BTT*FFF];           // doubles as attention-score buffer (same size)
__device__ float g_feats[BTT*NLL];
__device__ int   g_psi [(TT-1)*BB*NLL];

// ---------------------------------------------------------------------------
// Helpers
// ---------------------------------------------------------------------------
__device__ __forceinline__ float block_reduce_sum(float v, float* red) {
    int tid = threadIdx.x;
    red[tid] = v;
    __syncthreads();
    for (int s = blockDim.x >> 1; s > 0; s >>= 1) {
        if (tid < s) red[tid] += red[tid + s];
        __syncthreads();
    }
    float r = red[0];
    __syncthreads();
    return r;
}

__device__ __forceinline__ float gelu_exact(float x) {
    return 0.5f * x * (1.0f + erff(x * 0.70710678118654752440f));
}

// ---------------------------------------------------------------------------
// Embedding + LayerNorm:  x = LN(tok[id] + pos[t] + typ[0]) * g + b
// one block per row (B*T rows), 256 threads
// ---------------------------------------------------------------------------
__global__ void embed_ln_kernel(const int* __restrict__ ids,
                                const float* __restrict__ tok,
                                const float* __restrict__ pos,
                                const float* __restrict__ typ,
                                const float* __restrict__ gamma,
                                const float* __restrict__ beta) {
    __shared__ float sx[HH];
    __shared__ float red[256];
    int row = blockIdx.x;
    int t   = row & (TT - 1);
    int id  = ids[row];
    for (int h = threadIdx.x; h < HH; h += 256)
        sx[h] = tok[(size_t)id * HH + h] + pos[t * HH + h] + typ[h];
    __syncthreads();
    float s = 0.f;
    for (int h = threadIdx.x; h < HH; h += 256) s += sx[h];
    float mu = block_reduce_sum(s, red) * (1.0f / HH);
    float s2 = 0.f;
    for (int h = threadIdx.x; h < HH; h += 256) { float d = sx[h] - mu; s2 += d * d; }
    float var = block_reduce_sum(s2, red) * (1.0f / HH);
    float inv = rsqrtf(var + 1e-12f);
    for (int h = threadIdx.x; h < HH; h += 256)
        g_x[(size_t)row * HH + h] = (sx[h] - mu) * inv * gamma[h] + beta[h];
}

// ---------------------------------------------------------------------------
// Residual + LayerNorm:  out = LN(res + y) * g + b  (in-place safe: row buffered)
// ---------------------------------------------------------------------------
__global__ void ln_res_kernel(const float* __restrict__ res,
                              const float* __restrict__ y,
                              const float* __restrict__ gamma,
                              const float* __restrict__ beta,
                              float* __restrict__ out) {
    __shared__ float sx[HH];
    __shared__ float red[256];
    size_t base = (size_t)blockIdx.x * HH;
    for (int h = threadIdx.x; h < HH; h += 256)
        sx[h] = res[base + h] + y[base + h];
    __syncthreads();
    float s = 0.f;
    for (int h = threadIdx.x; h < HH; h += 256) s += sx[h];
    float mu = block_reduce_sum(s, red) * (1.0f / HH);
    float s2 = 0.f;
    for (int h = threadIdx.x; h < HH; h += 256) { float d = sx[h] - mu; s2 += d * d; }
    float var = block_reduce_sum(s2, red) * (1.0f / HH);
    float inv = rsqrtf(var + 1e-12f);
    for (int h = threadIdx.x; h < HH; h += 256)
        out[base + h] = (sx[h] - mu) * inv * gamma[h] + beta[h];
}

// ---------------------------------------------------------------------------
// Classic fp32 SGEMM: C[M,N] = act(A[M,K] @ B[K,N] + bias)
// 128x128 block tile, BK=8, 256 threads, 8x8 per-thread (4+4 split fragments)
// M,N multiples of 128; K multiple of 8.
// ---------------------------------------------------------------------------
__global__ __launch_bounds__(256, 2)
void sgemm_kernel(const float* __restrict__ A, const float* __restrict__ B,
                  const float* __restrict__ bias, float* __restrict__ C,
                  int M, int N, int K, int act) {
    __shared__ float As[8][128];
    __shared__ float Bs[8][128];
    const int tid = threadIdx.x;
    const int tx = tid & 15, ty = tid >> 4;
    const int bx = blockIdx.x, by = blockIdx.y;
    const float* Ab = A + (size_t)by * 128 * K;
    const float* Bb = B + bx * 128;
    const int arow = tid >> 1, acol = (tid & 1) << 2;
    const int brow = tid >> 5, bcol = (tid & 31) << 2;

    float acc[8][8];
#pragma unroll
    for (int i = 0; i < 8; i++)
#pragma unroll
        for (int j = 0; j < 8; j++) acc[i][j] = 0.f;

    for (int k0 = 0; k0 < K; k0 += 8) {
        float4 av = *(const float4*)(Ab + (size_t)arow * K + k0 + acol);
        As[acol + 0][arow] = av.x; As[acol + 1][arow] = av.y;
        As[acol + 2][arow] = av.z; As[acol + 3][arow] = av.w;
        *(float4*)(&Bs[brow][bcol]) = *(const float4*)(Bb + (size_t)(k0 + brow) * N + bcol);
        __syncthreads();
#pragma unroll
        for (int kk = 0; kk < 8; kk++) {
            float4 a0 = *(const float4*)&As[kk][ty * 4];
            float4 a1 = *(const float4*)&As[kk][64 + ty * 4];
            float4 b0 = *(const float4*)&Bs[kk][tx * 4];
            float4 b1 = *(const float4*)&Bs[kk][64 + tx * 4];
            float ar[8] = {a0.x, a0.y, a0.z, a0.w, a1.x, a1.y, a1.z, a1.w};
            float br[8] = {b0.x, b0.y, b0.z, b0.w, b1.x, b1.y, b1.z, b1.w};
#pragma unroll
            for (int i = 0; i < 8; i++)
#pragma unroll
                for (int j = 0; j < 8; j++) acc[i][j] += ar[i] * br[j];
        }
        __syncthreads();
    }
#pragma unroll
    for (int i = 0; i < 8; i++) {
        int r = by * 128 + ((i < 4) ? (ty * 4 + i) : (64 + ty * 4 + (i - 4)));
#pragma unroll
        for (int jh = 0; jh < 2; jh++) {
            int c = bx * 128 + jh * 64 + tx * 4;
            float o0 = acc[i][jh * 4 + 0] + bias[c + 0];
            float o1 = acc[i][jh * 4 + 1] + bias[c + 1];
            float o2 = acc[i][jh * 4 + 2] + bias[c + 2];
            float o3 = acc[i][jh * 4 + 3] + bias[c + 3];
            if (act == 1) { o0 = gelu_exact(o0); o1 = gelu_exact(o1); o2 = gelu_exact(o2); o3 = gelu_exact(o3); }
            float4 o = make_float4(o0, o1, o2, o3);
            *(float4*)(C + (size_t)r * N + c) = o;
        }
    }
}

// ---------------------------------------------------------------------------
// Attention scores: S[hb, 256, 256] = Q_h @ K_h^T * (1/8) + amask
// hb = b*NH + h. Q/K rows strided by HH. Grid (2,2,384), 256 threads.
// ---------------------------------------------------------------------------
__global__ __launch_bounds__(256, 2)
void attn_score_kernel(const float* __restrict__ Q, const float* __restrict__ Km,
                       const int* __restrict__ maskp, float* __restrict__ S) {
    __shared__ float As[8][128];
    __shared__ float Bs[8][128];
    const int hb = blockIdx.z;
    const int b = hb / NHH, h = hb % NHH;
    const float* Qb = Q + (size_t)b * TT * HH + h * DHH;
    const float* Kb = Km + (size_t)b * TT * HH + h * DHH;
    float* Sb = S + (size_t)hb * TT * TT;
    const int tid = threadIdx.x;
    const int tx = tid & 15, ty = tid >> 4;
    const int bx = blockIdx.x, by = blockIdx.y;
    const int arow = tid >> 1, acol = (tid & 1) << 2;
    const int nrow = tid >> 1, kg = (tid & 1) << 2;

    float acc[8][8];
#pragma unroll
    for (int i = 0; i < 8; i++)
#pragma unroll
        for (int j = 0; j < 8; j++) acc[i][j] = 0.f;

    for (int k0 = 0; k0 < DHH; k0 += 8) {
        float4 av = *(const float4*)(Qb + (size_t)(by * 128 + arow) * HH + k0 + acol);
        As[acol + 0][arow] = av.x; As[acol + 1][arow] = av.y;
        As[acol + 2][arow] = av.z; As[acol + 3][arow] = av.w;
        float4 kv = *(const float4*)(Kb + (size_t)(bx * 128 + nrow) * HH + k0 + kg);
        Bs[kg + 0][nrow] = kv.x; Bs[kg + 1][nrow] = kv.y;
        Bs[kg + 2][nrow] = kv.z; Bs[kg + 3][nrow] = kv.w;
        __syncthreads();
#pragma unroll
        for (int kk = 0; kk < 8; kk++) {
            float4 a0 = *(const float4*)&As[kk][ty * 4];
            float4 a1 = *(const float4*)&As[kk][64 + ty * 4];
            float4 b0 = *(const float4*)&Bs[kk][tx * 4];
            float4 b1 = *(const float4*)&Bs[kk][64 + tx * 4];
            float ar[8] = {a0.x, a0.y, a0.z, a0.w, a1.x, a1.y, a1.z, a1.w};
            float br[8] = {b0.x, b0.y, b0.z, b0.w, b1.x, b1.y, b1.z, b1.w};
#pragma unroll
            for (int i = 0; i < 8; i++)
#pragma unroll
                for (int j = 0; j < 8; j++) acc[i][j] += ar[i] * br[j];
        }
        __syncthreads();
    }
#pragma unroll
    for (int i = 0; i < 8; i++) {
        int r = by * 128 + ((i < 4) ? (ty * 4 + i) : (64 + ty * 4 + (i - 4)));
#pragma unroll
        for (int jh = 0; jh < 2; jh++) {
            int c = bx * 128 + jh * 64 + tx * 4;
            float4 o;
            o.x = acc[i][jh * 4 + 0] * 0.125f + (1.0f - (float)maskp[b * TT + c + 0]) * NEGV;
            o.y = acc[i][jh * 4 + 1] * 0.125f + (1.0f - (float)maskp[b * TT + c + 1]) * NEGV;
            o.z = acc[i][jh * 4 + 2] * 0.125f + (1.0f - (float)maskp[b * TT + c + 2]) * NEGV;
            o.w = acc[i][jh * 4 + 3] * 0.125f + (1.0f - (float)maskp[b * TT + c + 3]) * NEGV;
            *(float4*)(Sb + (size_t)r * TT + c) = o;
        }
    }
}

// ---------------------------------------------------------------------------
// Row softmax over 256 (one warp per row). exact expf to track fp32 reference.
// ---------------------------------------------------------------------------
__global__ void softmax_kernel(float* __restrict__ S) {
    int row  = blockIdx.x * 8 + (threadIdx.x >> 5);
    int lane = threadIdx.x & 31;
    float* r = S + (size_t)row * TT;
    float v[8];
    float mx = -3.4e38f;
#pragma unroll
    for (int i = 0; i < 8; i++) { v[i] = r[lane + 32 * i]; mx = fmaxf(mx, v[i]); }
#pragma unroll
    for (int off = 16; off; off >>= 1) mx = fmaxf(mx, __shfl_xor_sync(0xffffffffu, mx, off));
    float sum = 0.f;
#pragma unroll
    for (int i = 0; i < 8; i++) { v[i] = expf(v[i] - mx); sum += v[i]; }
#pragma unroll
    for (int off = 16; off; off >>= 1) sum += __shfl_xor_sync(0xffffffffu, sum, off);
    float inv = 1.0f / sum;
#pragma unroll
    for (int i = 0; i < 8; i++) r[lane + 32 * i] = v[i] * inv;
}

// ---------------------------------------------------------------------------
// ctx_h = P_h @ V_h  : per head [256,256]@[256,64]. 128 threads, 128x64 tile.
// Grid (1, 2, 384).
// ---------------------------------------------------------------------------
__global__ __launch_bounds__(128, 4)
void attn_pv_kernel(const float* __restrict__ P, const float* __restrict__ V,
                    float* __restrict__ ctx) {
    __shared__ float As[8][128];
    __shared__ float Bs[8][64];
    const int hb = blockIdx.z;
    const int b = hb / NHH, h = hb % NHH;
    const float* Pb = P + (size_t)hb * TT * TT;
    const float* Vb = V + (size_t)b * TT * HH + h * DHH;
    float* Cb = ctx + (size_t)b * TT * HH + h * DHH;
    const int by = blockIdx.y;
    const int tid = threadIdx.x;
    const int tx = tid & 7, ty = tid >> 3;
    const int brow = tid >> 4, bcol = (tid & 15) << 2;

    float acc[8][8];
#pragma unroll
    for (int i = 0; i < 8; i++)
#pragma unroll
        for (int j = 0; j < 8; j++) acc[i][j] = 0.f;

    for (int k0 = 0; k0 < TT; k0 += 8) {
        float4 a0 = *(const float4*)(Pb + (size_t)(by * 128 + tid) * TT + k0);
        float4 a1 = *(const float4*)(Pb + (size_t)(by * 128 + tid) * TT + k0 + 4);
        As[0][tid] = a0.x; As[1][tid] = a0.y; As[2][tid] = a0.z; As[3][tid] = a0.w;
        As[4][tid] = a1.x; As[5][tid] = a1.y; As[6][tid] = a1.z; As[7][tid] = a1.w;
        *(float4*)(&Bs[brow][bcol]) = *(const float4*)(Vb + (size_t)(k0 + brow) * HH + bcol);
        __syncthreads();
#pragma unroll
        for (int kk = 0; kk < 8; kk++) {
            float4 aa0 = *(const float4*)&As[kk][ty * 4];
            float4 aa1 = *(const float4*)&As[kk][64 + ty * 4];
            float4 bb0 = *(const float4*)&Bs[kk][tx * 4];
            float4 bb1 = *(const float4*)&Bs[kk][32 + tx * 4];
            float ar[8] = {aa0.x, aa0.y, aa0.z, aa0.w, aa1.x, aa1.y, aa1.z, aa1.w};
            float br[8] = {bb0.x, bb0.y, bb0.z, bb0.w, bb1.x, bb1.y, bb1.z, bb1.w};
#pragma unroll
            for (int i = 0; i < 8; i++)
#pragma unroll
                for (int j = 0; j < 8; j++) acc[i][j] += ar[i] * br[j];
        }
        __syncthreads();
    }
#pragma unroll
    for (int i = 0; i < 8; i++) {
        int r = by * 128 + ((i < 4) ? (ty * 4 + i) : (64 + ty * 4 + (i - 4)));
#pragma unroll
        for (int jh = 0; jh < 2; jh++) {
            int c = jh * 32 + tx * 4;
            float4 o = make_float4(acc[i][jh * 4 + 0], acc[i][jh * 4 + 1],
                                   acc[i][jh * 4 + 2], acc[i][jh * 4 + 3]);
            *(float4*)(Cb + (size_t)r * HH + c) = o;
        }
    }
}

// ---------------------------------------------------------------------------
// feats = x @ lab_W + lab_b  :  [8192,768]@[768,31]
// one block per row; 256 threads = 8 partials x 32 states
// ---------------------------------------------------------------------------
__global__ void feats_kernel(const float* __restrict__ X, const float* __restrict__ W,
                             const float* __restrict__ bias, float* __restrict__ F) {
    __shared__ float sx[HH];
    __shared__ float red[8][32];
    int row = blockIdx.x;
    for (int h = threadIdx.x; h < HH; h += 256) sx[h] = X[(size_t)row * HH + h];
    __syncthreads();
    int j = threadIdx.x & 31, part = threadIdx.x >> 5;
    float s = 0.f;
    if (j < NLL) {
        int k0 = part * 96;
#pragma unroll 4
        for (int k = k0; k < k0 + 96; k++) s += sx[k] * W[k * NLL + j];
    }
    red[part][j] = s;
    __syncthreads();
    if (part == 0 && j < NLL) {
        float tot = bias[j];
#pragma unroll
        for (int p = 0; p < 8; p++) tot += red[p][j];
        F[row * NLL + j] = tot;
    }
}

// ---------------------------------------------------------------------------
// Viterbi decode. One block, 32 warps: warp b handles batch b; lane j = state.
// Matches jnp.argmax first-occurrence tie-breaking.
// Writes score + path to out (as float), layout depends on out_size.
// ---------------------------------------------------------------------------
__global__ void viterbi_kernel(const float* __restrict__ F, const float* __restrict__ trans,
                               float* __restrict__ out, int out_size) {
    __shared__ float tr[NLL][32];
    int tid = threadIdx.x;
    for (int i = tid; i < NLL * NLL; i += blockDim.x)
        tr[i / NLL][i % NLL] = trans[i];
    __syncthreads();
    int b = tid >> 5, j = tid & 31;
    int jc = (j < NLL) ? j : 0;
    float ld = (j == START_S) ? 0.0f : NEGV;
    if (j >= NLL) ld = -1e30f;
    for (int t = 1; t < TT; t++) {
        float best = -3.4e38f; int bp = 0;
#pragma unroll
        for (int prev = 0; prev < NLL; prev++) {
            float ldp = __shfl_sync(0xffffffffu, ld, prev);
            float v = tr[jc][prev] + ldp;
            if (v > best) { best = v; bp = prev; }
        }
        if (j < NLL) g_psi[((t - 1) * BB + b) * NLL + j] = bp;
        float f = (j < NLL) ? F[((size_t)b * TT + t) * NLL + j] : 0.f;
        ld = best + f;
        if (j >= NLL) ld = -1e30f;
    }
    // argmax over lanes 0..30 (first occurrence on ties)
    float val = (j < NLL) ? ld : -3.4e38f;
    int idx = jc;
#pragma unroll
    for (int off = 16; off; off >>= 1) {
        float ov = __shfl_xor_sync(0xffffffffu, val, off);
        int   oi = __shfl_xor_sync(0xffffffffu, idx, off);
        if (ov > val || (ov == val && oi < idx)) { val = ov; idx = oi; }
    }
    if (j == 0) {
        float* score_out = out;
        float* path_out  = out + BB;
        bool have_score = true, have_path = true;
        if (out_size >= BB + BB * TT) { /* default layout */ }
        else if (out_size >= BB * TT) { have_score = false; path_out = out; }
        else { have_path = false; }
        if (have_score) score_out[b] = val;
        if (have_path) {
            int p = idx;
            path_out[b * TT + TT - 1] = (float)p;
            for (int t = TT - 1; t >= 1; t--) {
                p = g_psi[((t - 1) * BB + b) * NLL + p];
                path_out[b * TT + t - 1] = (float)p;
            }
        }
    }
}

// ---------------------------------------------------------------------------
// Launcher
// ---------------------------------------------------------------------------
extern "C" void kernel_launch(void* const* d_in, const int* in_sizes, int n_in,
                              void* d_out, int out_size) {
    const int*   ids    = (const int*)  d_in[0];
    const int*   maskp  = (const int*)  d_in[1];
    const float* tok    = (const float*)d_in[2];
    const float* pos    = (const float*)d_in[3];
    const float* typ    = (const float*)d_in[4];
    const float* eg     = (const float*)d_in[5];
    const float* eb     = (const float*)d_in[6];
    const float* Wq_all = (const float*)d_in[7];
    const float* bq_all = (const float*)d_in[8];
    const float* Wk_all = (const float*)d_in[9];
    const float* bk_all = (const float*)d_in[10];
    const float* Wv_all = (const float*)d_in[11];
    const float* bv_all = (const float*)d_in[12];
    const float* Wo_all = (const float*)d_in[13];
    const float* bo_all = (const float*)d_in[14];
    const float* ln1g   = (const float*)d_in[15];
    const float* ln1b   = (const float*)d_in[16];
    const float* W1_all = (const float*)d_in[17];
    const float* b1_all = (const float*)d_in[18];
    const float* W2_all = (const float*)d_in[19];
    const float* b2_all = (const float*)d_in[20];
    const float* ln2g   = (const float*)d_in[21];
    const float* ln2b   = (const float*)d_in[22];
    const float* labW   = (const float*)d_in[23];
    const float* labb   = (const float*)d_in[24];
    const float* trans  = (const float*)d_in[25];
    float* out = (float*)d_out;

    static float *p_x = nullptr, *p_q, *p_k, *p_v, *p_ctx, *p_t1, *p_ff, *p_feats;
    if (!p_x) {
        cudaGetSymbolAddress((void**)&p_x,    g_x);
        cudaGetSymbolAddress((void**)&p_q,    g_q);
        cudaGetSymbolAddress((void**)&p_k,    g_k);
        cudaGetSymbolAddress((void**)&p_v,    g_v);
        cudaGetSymbolAddress((void**)&p_ctx,  g_ctx);
        cudaGetSymbolAddress((void**)&p_t1,   g_t1);
        cudaGetSymbolAddress((void**)&p_ff,   g_ff);
        cudaGetSymbolAddress((void**)&p_feats,g_feats);
    }

    embed_ln_kernel<<<BTT, 256>>>(ids, tok, pos, typ, eg, eb);

    dim3 gHH(HH / 128, BTT / 128);    // 6 x 64
    dim3 gFF(FFF / 128, BTT / 128);   // 24 x 64
    dim3 gScore(2, 2, BB * NHH);      // 2x2x384
    dim3 gPV(1, 2, BB * NHH);         // 1x2x384

    for (int l = 0; l < LL; l++) {
        const float* Wq = Wq_all + (size_t)l * HH * HH;
        const float* Wk = Wk_all + (size_t)l * HH * HH;
        const float* Wv = Wv_all + (size_t)l * HH * HH;
        const float* Wo = Wo_all + (size_t)l * HH * HH;
        const float* W1 = W1_all + (size_t)l * HH * FFF;
        const float* W2 = W2_all + (size_t)l * FFF * HH;
        const float* bq = bq_all + l * HH;
        const float* bk = bk_all + l * HH;
        const float* bv = bv_all + l * HH;
        const float* bo = bo_all + l * HH;
        const float* b1 = b1_all + l * FFF;
        const float* b2 = b2_all + l * HH;
        const float* g1 = ln1g + l * HH; const float* be1 = ln1b + l * HH;
        const float* g2 = ln2g + l * HH; const float* be2 = ln2b + l * HH;

        sgemm_kernel<<<gHH, 256>>>(p_x, Wq, bq, p_q, BTT, HH, HH, 0);
        sgemm_kernel<<<gHH, 256>>>(p_x, Wk, bk, p_k, BTT, HH, HH, 0);
        sgemm_kernel<<<gHH, 256>>>(p_x, Wv, bv, p_v, BTT, HH, HH, 0);

        attn_score_kernel<<<gScore, 256>>>(p_q, p_k, maskp, p_ff);
        softmax_kernel<<<(BB * NHH * TT) / 8, 256>>>(p_ff);
        attn_pv_kernel<<<gPV, 128>>>(p_ff, p_v, p_ctx);

        sgemm_kernel<<<gHH, 256>>>(p_ctx, Wo, bo, p_t1, BTT, HH, HH, 0);
        ln_res_kernel<<<BTT, 256>>>(p_x, p_t1, g1, be1, p_x);

        sgemm_kernel<<<gFF, 256>>>(p_x, W1, b1, p_ff, BTT, FFF, HH, 1);
        sgemm_kernel<<<gHH, 256>>>(p_ff, W2, b2, p_t1, BTT, HH, FFF, 0);
        ln_res_kernel<<<BTT, 256>>>(p_x, p_t1, g2, be2, p_x);
    }

    feats_kernel<<<BTT, 256>>>(p_x, labW, labb, p_feats);
    viterbi_kernel<<<1, 1024>>>(p_feats, trans, out, out_size);
}